// round 2
// baseline (speedup 1.0000x reference)
#include <cuda_runtime.h>
#include <math.h>

#define Tn 2048
#define Bn 4
#define En 512
#define Hn 8
#define HDn 64
#define BHn 32
#define TBn 8192
#define SCALE_F 0.125f

// Scratch (allocation-free rule: __device__ globals)
__device__ float g_q[BHn * Tn * HDn];          // [b*H+h][t][d], pre-scaled
__device__ float g_k[BHn * Tn * HDn];
__device__ float g_v[BHn * Tn * HDn];
__device__ float g_o[BHn * Tn * HDn];          // attention output pre-projection
__device__ float g_s[134217728];               // [b*H+h][q][k]  (536 MB)

// ---------------------------------------------------------------------------
// Kernel 1: QKV projection.  C[m,n] = sum_e X[m,e]*W[n,e] + bias[n]
// m = t*B+b over [0,8192), n over [0,1536). Routed to g_q (scaled), g_k, g_v.
// 128x128 tile, 16-deep k-chunks, 8x8 micro-tile per thread (256 threads).
// ---------------------------------------------------------------------------
__global__ __launch_bounds__(256) void k_qkv(const float* __restrict__ X,
                                             const float* __restrict__ W,
                                             const float* __restrict__ Bv) {
    __shared__ float As[16][132];
    __shared__ float Bs[16][132];
    const int tid = threadIdx.x;
    const int tx = tid & 15, ty = tid >> 4;
    const int m0 = blockIdx.y * 128, n0 = blockIdx.x * 128;
    const int lrow = tid >> 2;
    const int lk4 = (tid & 3) << 2;

    float acc[8][8];
#pragma unroll
    for (int i = 0; i < 8; i++)
#pragma unroll
        for (int j = 0; j < 8; j++) acc[i][j] = 0.f;

    for (int k0 = 0; k0 < En; k0 += 16) {
#pragma unroll
        for (int hh = 0; hh < 2; hh++) {
            int r = lrow + hh * 64;
            float4 av = *(const float4*)&X[(size_t)(m0 + r) * En + k0 + lk4];
            As[lk4 + 0][r] = av.x; As[lk4 + 1][r] = av.y;
            As[lk4 + 2][r] = av.z; As[lk4 + 3][r] = av.w;
            float4 bv = *(const float4*)&W[(size_t)(n0 + r) * En + k0 + lk4];
            Bs[lk4 + 0][r] = bv.x; Bs[lk4 + 1][r] = bv.y;
            Bs[lk4 + 2][r] = bv.z; Bs[lk4 + 3][r] = bv.w;
        }
        __syncthreads();
#pragma unroll
        for (int kk = 0; kk < 16; kk++) {
            float a[8], b[8];
            *(float4*)(a)     = *(const float4*)&As[kk][ty * 4];
            *(float4*)(a + 4) = *(const float4*)&As[kk][64 + ty * 4];
            *(float4*)(b)     = *(const float4*)&Bs[kk][tx * 4];
            *(float4*)(b + 4) = *(const float4*)&Bs[kk][64 + tx * 4];
#pragma unroll
            for (int i = 0; i < 8; i++)
#pragma unroll
                for (int j = 0; j < 8; j++) acc[i][j] += a[i] * b[j];
        }
        __syncthreads();
    }

    const int which = n0 >> 9;  // tile never crosses a 512 boundary (128 | 512)
    float* dst = which == 0 ? g_q : (which == 1 ? g_k : g_v);
    const float mul = (which == 0) ? SCALE_F : 1.0f;

#pragma unroll
    for (int i = 0; i < 8; i++) {
        int m = m0 + ((i < 4) ? (ty * 4 + i) : (64 + ty * 4 + (i - 4)));
        int t = m >> 2, b = m & 3;
#pragma unroll
        for (int jh = 0; jh < 2; jh++) {
            int n = n0 + jh * 64 + tx * 4;
            int e = n & 511;
            int h = e >> 6, d = e & 63;
            float4 v;
            v.x = (acc[i][jh * 4 + 0] + Bv[n + 0]) * mul;
            v.y = (acc[i][jh * 4 + 1] + Bv[n + 1]) * mul;
            v.z = (acc[i][jh * 4 + 2] + Bv[n + 2]) * mul;
            v.w = (acc[i][jh * 4 + 3] + Bv[n + 3]) * mul;
            *(float4*)&dst[((size_t)(b * Hn + h) * Tn + t) * HDn + d] = v;
        }
    }
}

// ---------------------------------------------------------------------------
// Kernel 2: scores S = Q @ K^T per (b,h). M=N=2048, Kdim=64.
// ---------------------------------------------------------------------------
__global__ __launch_bounds__(256) void k_scores() {
    __shared__ float As[16][132];
    __shared__ float Bs[16][132];
    const int tid = threadIdx.x;
    const int tx = tid & 15, ty = tid >> 4;
    const int bh = blockIdx.z;
    const float* Q = g_q + (size_t)bh * Tn * HDn;
    const float* K = g_k + (size_t)bh * Tn * HDn;
    float* S = g_s + (size_t)bh * Tn * Tn;
    const int m0 = blockIdx.y * 128, n0 = blockIdx.x * 128;
    const int lrow = tid >> 2;
    const int lk4 = (tid & 3) << 2;

    float acc[8][8];
#pragma unroll
    for (int i = 0; i < 8; i++)
#pragma unroll
        for (int j = 0; j < 8; j++) acc[i][j] = 0.f;

    for (int k0 = 0; k0 < HDn; k0 += 16) {
#pragma unroll
        for (int hh = 0; hh < 2; hh++) {
            int r = lrow + hh * 64;
            float4 av = *(const float4*)&Q[(size_t)(m0 + r) * HDn + k0 + lk4];
            As[lk4 + 0][r] = av.x; As[lk4 + 1][r] = av.y;
            As[lk4 + 2][r] = av.z; As[lk4 + 3][r] = av.w;
            float4 bv = *(const float4*)&K[(size_t)(n0 + r) * HDn + k0 + lk4];
            Bs[lk4 + 0][r] = bv.x; Bs[lk4 + 1][r] = bv.y;
            Bs[lk4 + 2][r] = bv.z; Bs[lk4 + 3][r] = bv.w;
        }
        __syncthreads();
#pragma unroll
        for (int kk = 0; kk < 16; kk++) {
            float a[8], b[8];
            *(float4*)(a)     = *(const float4*)&As[kk][ty * 4];
            *(float4*)(a + 4) = *(const float4*)&As[kk][64 + ty * 4];
            *(float4*)(b)     = *(const float4*)&Bs[kk][tx * 4];
            *(float4*)(b + 4) = *(const float4*)&Bs[kk][64 + tx * 4];
#pragma unroll
            for (int i = 0; i < 8; i++)
#pragma unroll
                for (int j = 0; j < 8; j++) acc[i][j] += a[i] * b[j];
        }
        __syncthreads();
    }

#pragma unroll
    for (int i = 0; i < 8; i++) {
        int m = m0 + ((i < 4) ? (ty * 4 + i) : (64 + ty * 4 + (i - 4)));
#pragma unroll
        for (int jh = 0; jh < 2; jh++) {
            int n = n0 + jh * 64 + tx * 4;
            float4 v = make_float4(acc[i][jh * 4 + 0], acc[i][jh * 4 + 1],
                                   acc[i][jh * 4 + 2], acc[i][jh * 4 + 3]);
            *(float4*)&S[(size_t)m * Tn + n] = v;
        }
    }
}

// ---------------------------------------------------------------------------
// Kernel 3: softmax over last dim of S, in place. One CTA per row (2048).
// Row held in registers: 1 read + 1 write of 536 MB.
// ---------------------------------------------------------------------------
__global__ __launch_bounds__(256) void k_softmax() {
    __shared__ float redA[8];
    __shared__ float redB[8];
    __shared__ float sh_m, sh_inv;
    const int tid = threadIdx.x;
    const int lane = tid & 31, wid = tid >> 5;
    const size_t base = (size_t)blockIdx.x * Tn;

    float4 v0 = *(const float4*)&g_s[base + tid * 4];
    float4 v1 = *(const float4*)&g_s[base + 1024 + tid * 4];

    float m = fmaxf(fmaxf(fmaxf(v0.x, v0.y), fmaxf(v0.z, v0.w)),
                    fmaxf(fmaxf(v1.x, v1.y), fmaxf(v1.z, v1.w)));
#pragma unroll
    for (int o = 16; o; o >>= 1) m = fmaxf(m, __shfl_xor_sync(0xffffffffu, m, o));
    if (lane == 0) redA[wid] = m;
    __syncthreads();
    if (tid == 0) {
        float t = redA[0];
#pragma unroll
        for (int i = 1; i < 8; i++) t = fmaxf(t, redA[i]);
        sh_m = t;
    }
    __syncthreads();
    m = sh_m;

    v0.x = __expf(v0.x - m); v0.y = __expf(v0.y - m);
    v0.z = __expf(v0.z - m); v0.w = __expf(v0.w - m);
    v1.x = __expf(v1.x - m); v1.y = __expf(v1.y - m);
    v1.z = __expf(v1.z - m); v1.w = __expf(v1.w - m);

    float s = v0.x + v0.y + v0.z + v0.w + v1.x + v1.y + v1.z + v1.w;
#pragma unroll
    for (int o = 16; o; o >>= 1) s += __shfl_xor_sync(0xffffffffu, s, o);
    if (lane == 0) redB[wid] = s;
    __syncthreads();
    if (tid == 0) {
        float t = 0.f;
#pragma unroll
        for (int i = 0; i < 8; i++) t += redB[i];
        sh_inv = 1.0f / t;
    }
    __syncthreads();
    const float inv = sh_inv;

    v0.x *= inv; v0.y *= inv; v0.z *= inv; v0.w *= inv;
    v1.x *= inv; v1.y *= inv; v1.z *= inv; v1.w *= inv;
    *(float4*)&g_s[base + tid * 4] = v0;
    *(float4*)&g_s[base + 1024 + tid * 4] = v1;
}

// ---------------------------------------------------------------------------
// Kernel 4: avg_weights[b,q,k] = (1/H) sum_h P[b,h,q,k]. CTA per (b,q) row.
// ---------------------------------------------------------------------------
__global__ __launch_bounds__(256) void k_avg(float* __restrict__ avg) {
    const int r = blockIdx.x;          // b*T + q
    const int b = r >> 11, q = r & 2047;
    const int tid = threadIdx.x;
    const size_t obase = (size_t)r * Tn;
#pragma unroll
    for (int half = 0; half < 2; half++) {
        int c = tid * 4 + half * 1024;
        float4 s = make_float4(0.f, 0.f, 0.f, 0.f);
#pragma unroll
        for (int h = 0; h < 8; h++) {
            float4 v = *(const float4*)&g_s[((size_t)(b * Hn + h) * Tn + q) * Tn + c];
            s.x += v.x; s.y += v.y; s.z += v.z; s.w += v.w;
        }
        s.x *= 0.125f; s.y *= 0.125f; s.z *= 0.125f; s.w *= 0.125f;
        *(float4*)&avg[obase + c] = s;
    }
}

// ---------------------------------------------------------------------------
// Kernel 5: O = P @ V per (b,h). M=2048, Kdim=2048, N=64.
// Tile 128(M) x 64(N), 8x4 micro-tile.
// ---------------------------------------------------------------------------
__global__ __launch_bounds__(256) void k_pv() {
    __shared__ float As[16][132];
    __shared__ float Bs[16][68];
    const int tid = threadIdx.x;
    const int tx = tid & 15, ty = tid >> 4;
    const int bh = blockIdx.z;
    const float* P = g_s + (size_t)bh * Tn * Tn;
    const float* V = g_v + (size_t)bh * Tn * HDn;
    const int m0 = blockIdx.y * 128;
    const int lrow = tid >> 2;
    const int lk4 = (tid & 3) << 2;
    const int bkk = tid >> 4;          // 0..15
    const int bnc = (tid & 15) << 2;   // 0..60

    float acc[8][4];
#pragma unroll
    for (int i = 0; i < 8; i++)
#pragma unroll
        for (int j = 0; j < 4; j++) acc[i][j] = 0.f;

    for (int k0 = 0; k0 < Tn; k0 += 16) {
#pragma unroll
        for (int hh = 0; hh < 2; hh++) {
            int r = lrow + hh * 64;
            float4 av = *(const float4*)&P[(size_t)(m0 + r) * Tn + k0 + lk4];
            As[lk4 + 0][r] = av.x; As[lk4 + 1][r] = av.y;
            As[lk4 + 2][r] = av.z; As[lk4 + 3][r] = av.w;
        }
        float4 bv = *(const float4*)&V[(size_t)(k0 + bkk) * HDn + bnc];
        *(float4*)&Bs[bkk][bnc] = bv;
        __syncthreads();
#pragma unroll
        for (int kk = 0; kk < 16; kk++) {
            float a[8], b[4];
            *(float4*)(a)     = *(const float4*)&As[kk][ty * 4];
            *(float4*)(a + 4) = *(const float4*)&As[kk][64 + ty * 4];
            *(float4*)(b)     = *(const float4*)&Bs[kk][tx * 4];
#pragma unroll
            for (int i = 0; i < 8; i++)
#pragma unroll
                for (int j = 0; j < 4; j++) acc[i][j] += a[i] * b[j];
        }
        __syncthreads();
    }

#pragma unroll
    for (int i = 0; i < 8; i++) {
        int m = m0 + ((i < 4) ? (ty * 4 + i) : (64 + ty * 4 + (i - 4)));
        float4 v = make_float4(acc[i][0], acc[i][1], acc[i][2], acc[i][3]);
        *(float4*)&g_o[((size_t)bh * Tn + m) * HDn + tx * 4] = v;
    }
}

// ---------------------------------------------------------------------------
// Kernel 6: out projection. out[m,n] = sum_e A[m,e]*W2[n,e] + b2[n]
// A[m,e] gathered from g_o: m=(t,b), e=(h,d). Writes attn part of d_out.
// ---------------------------------------------------------------------------
__global__ __launch_bounds__(256) void k_outproj(const float* __restrict__ W2,
                                                 const float* __restrict__ B2,
                                                 float* __restrict__ out) {
    __shared__ float As[16][132];
    __shared__ float Bs[16][132];
    const int tid = threadIdx.x;
    const int tx = tid & 15, ty = tid >> 4;
    const int m0 = blockIdx.y * 128, n0 = blockIdx.x * 128;
    const int lrow = tid >> 2;
    const int lk4 = (tid & 3) << 2;

    float acc[8][8];
#pragma unroll
    for (int i = 0; i < 8; i++)
#pragma unroll
        for (int j = 0; j < 8; j++) acc[i][j] = 0.f;

    for (int k0 = 0; k0 < En; k0 += 16) {
        int e = k0 + lk4;
        int h = e >> 6, d = e & 63;
#pragma unroll
        for (int hh = 0; hh < 2; hh++) {
            int r = lrow + hh * 64;
            int m = m0 + r;
            int t = m >> 2, b = m & 3;
            float4 av = *(const float4*)&g_o[((size_t)(b * Hn + h) * Tn + t) * HDn + d];
            As[lk4 + 0][r] = av.x; As[lk4 + 1][r] = av.y;
            As[lk4 + 2][r] = av.z; As[lk4 + 3][r] = av.w;
            float4 bv = *(const float4*)&W2[(size_t)(n0 + r) * En + k0 + lk4];
            Bs[lk4 + 0][r] = bv.x; Bs[lk4 + 1][r] = bv.y;
            Bs[lk4 + 2][r] = bv.z; Bs[lk4 + 3][r] = bv.w;
        }
        __syncthreads();
#pragma unroll
        for (int kk = 0; kk < 16; kk++) {
            float a[8], b[8];
            *(float4*)(a)     = *(const float4*)&As[kk][ty * 4];
            *(float4*)(a + 4) = *(const float4*)&As[kk][64 + ty * 4];
            *(float4*)(b)     = *(const float4*)&Bs[kk][tx * 4];
            *(float4*)(b + 4) = *(const float4*)&Bs[kk][64 + tx * 4];
#pragma unroll
            for (int i = 0; i < 8; i++)
#pragma unroll
                for (int j = 0; j < 8; j++) acc[i][j] += a[i] * b[j];
        }
        __syncthreads();
    }

#pragma unroll
    for (int i = 0; i < 8; i++) {
        int m = m0 + ((i < 4) ? (ty * 4 + i) : (64 + ty * 4 + (i - 4)));
#pragma unroll
        for (int jh = 0; jh < 2; jh++) {
            int n = n0 + jh * 64 + tx * 4;
            float4 v;
            v.x = acc[i][jh * 4 + 0] + B2[n + 0];
            v.y = acc[i][jh * 4 + 1] + B2[n + 1];
            v.z = acc[i][jh * 4 + 2] + B2[n + 2];
            v.w = acc[i][jh * 4 + 3] + B2[n + 3];
            *(float4*)&out[(size_t)m * En + n] = v;
        }
    }
}

// ---------------------------------------------------------------------------
extern "C" void kernel_launch(void* const* d_in, const int* in_sizes, int n_in,
                              void* d_out, int out_size) {
    (void)in_sizes; (void)n_in; (void)out_size;
    const float* x  = (const float*)d_in[0];
    const float* w  = (const float*)d_in[1];
    const float* bi = (const float*)d_in[2];
    const float* w2 = (const float*)d_in[3];
    const float* b2 = (const float*)d_in[4];
    float* out = (float*)d_out;

    k_qkv<<<dim3(12, 64), 256>>>(x, w, bi);                 // QKV projection
    k_scores<<<dim3(16, 16, 32), 256>>>();                  // S = Q K^T
    k_softmax<<<BHn * Tn, 256>>>();                         // softmax rows
    k_avg<<<Bn * Tn, 256>>>(out + (size_t)TBn * En);        // head-avg weights
    k_pv<<<dim3(1, 16, 32), 256>>>();                       // O = P V
    k_outproj<<<dim3(4, 64), 256>>>(w2, b2, out);           // out projection
}

// round 4
// speedup vs baseline: 1.5639x; 1.5639x over previous
#include <cuda_runtime.h>
#include <math.h>

#define Tn 2048
#define Bn 4
#define En 512
#define Hn 8
#define HDn 64
#define BHn 32
#define TBn 8192
#define SCALE_F 0.125f

// Scratch (allocation-free rule: __device__ globals)
__device__ float g_q[BHn * Tn * HDn];          // [b*H+h][t][d], pre-scaled
__device__ float g_k[BHn * Tn * HDn];
__device__ float g_v[BHn * Tn * HDn];
__device__ float g_vt[BHn * HDn * Tn];         // V transposed: [bh][d][t]
__device__ float g_o[BHn * Tn * HDn];          // attention output pre-projection
__device__ float g_s[134217728];               // [b*H+h][q][k]  (536 MB)

// ---------------------------------------------------------------------------
// tf32 mma helpers
// ---------------------------------------------------------------------------
__device__ __forceinline__ unsigned f2tf(float x) {
    unsigned r;
    asm("cvt.rna.tf32.f32 %0, %1;" : "=r"(r) : "f"(x));
    return r;
}

__device__ __forceinline__ void mma_tf32(float* c, const unsigned* a, const unsigned* b) {
    asm volatile(
        "mma.sync.aligned.m16n8k8.row.col.f32.tf32.tf32.f32 "
        "{%0,%1,%2,%3}, {%4,%5,%6,%7}, {%8,%9}, {%0,%1,%2,%3};"
        : "+f"(c[0]), "+f"(c[1]), "+f"(c[2]), "+f"(c[3])
        : "r"(a[0]), "r"(a[1]), "r"(a[2]), "r"(a[3]), "r"(b[0]), "r"(b[1]));
}

// ---------------------------------------------------------------------------
// Kernel 1: QKV projection (scalar, unchanged).
// ---------------------------------------------------------------------------
__global__ __launch_bounds__(256) void k_qkv(const float* __restrict__ X,
                                             const float* __restrict__ W,
                                             const float* __restrict__ Bv) {
    __shared__ float As[16][132];
    __shared__ float Bs[16][132];
    const int tid = threadIdx.x;
    const int tx = tid & 15, ty = tid >> 4;
    const int m0 = blockIdx.y * 128, n0 = blockIdx.x * 128;
    const int lrow = tid >> 2;
    const int lk4 = (tid & 3) << 2;

    float acc[8][8];
#pragma unroll
    for (int i = 0; i < 8; i++)
#pragma unroll
        for (int j = 0; j < 8; j++) acc[i][j] = 0.f;

    for (int k0 = 0; k0 < En; k0 += 16) {
#pragma unroll
        for (int hh = 0; hh < 2; hh++) {
            int r = lrow + hh * 64;
            float4 av = *(const float4*)&X[(size_t)(m0 + r) * En + k0 + lk4];
            As[lk4 + 0][r] = av.x; As[lk4 + 1][r] = av.y;
            As[lk4 + 2][r] = av.z; As[lk4 + 3][r] = av.w;
            float4 bv = *(const float4*)&W[(size_t)(n0 + r) * En + k0 + lk4];
            Bs[lk4 + 0][r] = bv.x; Bs[lk4 + 1][r] = bv.y;
            Bs[lk4 + 2][r] = bv.z; Bs[lk4 + 3][r] = bv.w;
        }
        __syncthreads();
#pragma unroll
        for (int kk = 0; kk < 16; kk++) {
            float a[8], b[8];
            *(float4*)(a)     = *(const float4*)&As[kk][ty * 4];
            *(float4*)(a + 4) = *(const float4*)&As[kk][64 + ty * 4];
            *(float4*)(b)     = *(const float4*)&Bs[kk][tx * 4];
            *(float4*)(b + 4) = *(const float4*)&Bs[kk][64 + tx * 4];
#pragma unroll
            for (int i = 0; i < 8; i++)
#pragma unroll
                for (int j = 0; j < 8; j++) acc[i][j] += a[i] * b[j];
        }
        __syncthreads();
    }

    const int which = n0 >> 9;
    float* dst = which == 0 ? g_q : (which == 1 ? g_k : g_v);
    const float mul = (which == 0) ? SCALE_F : 1.0f;

#pragma unroll
    for (int i = 0; i < 8; i++) {
        int m = m0 + ((i < 4) ? (ty * 4 + i) : (64 + ty * 4 + (i - 4)));
        int t = m >> 2, b = m & 3;
#pragma unroll
        for (int jh = 0; jh < 2; jh++) {
            int n = n0 + jh * 64 + tx * 4;
            int e = n & 511;
            int h = e >> 6, d = e & 63;
            float4 v;
            v.x = (acc[i][jh * 4 + 0] + Bv[n + 0]) * mul;
            v.y = (acc[i][jh * 4 + 1] + Bv[n + 1]) * mul;
            v.z = (acc[i][jh * 4 + 2] + Bv[n + 2]) * mul;
            v.w = (acc[i][jh * 4 + 3] + Bv[n + 3]) * mul;
            *(float4*)&dst[((size_t)(b * Hn + h) * Tn + t) * HDn + d] = v;
        }
    }
}

// ---------------------------------------------------------------------------
// Kernel 1b: V transpose  g_vt[bh][d][t] = g_v[bh][t][d]
// ---------------------------------------------------------------------------
__global__ __launch_bounds__(256) void k_vt() {
    __shared__ float ts[32][33];
    const int bh = blockIdx.z;
    const int t0 = blockIdx.x * 32, d0 = blockIdx.y * 32;
    const float* V = g_v + (size_t)bh * Tn * HDn;
    float* Vt = g_vt + (size_t)bh * HDn * Tn;
    const int lx = threadIdx.x & 31, ly = threadIdx.x >> 5;
#pragma unroll
    for (int p = 0; p < 4; p++) {
        int row = ly + p * 8;
        ts[row][lx] = V[(size_t)(t0 + row) * HDn + d0 + lx];
    }
    __syncthreads();
#pragma unroll
    for (int p = 0; p < 4; p++) {
        int row = ly + p * 8;
        Vt[(size_t)(d0 + row) * Tn + t0 + lx] = ts[lx][row];
    }
}

// ---------------------------------------------------------------------------
// Kernel 2: scores S = Q @ K^T per (b,h), tf32 mma. CTA tile 128x128, K=64.
// 8 warps as 2(m) x 4(n); warp tile 64x32 = 4x4 m16n8 mma tiles.
// ---------------------------------------------------------------------------
__global__ __launch_bounds__(256) void k_scores_mma() {
    __shared__ float Qs[128][36];
    __shared__ float Ks[128][36];
    const int tid = threadIdx.x;
    const int wid = tid >> 5, lane = tid & 31;
    const int g = lane >> 2, tig = lane & 3;
    const int warp_m = wid >> 2, warp_n = wid & 3;
    const int bh = blockIdx.z;
    const float* Q = g_q + (size_t)bh * Tn * HDn;
    const float* K = g_k + (size_t)bh * Tn * HDn;
    float* S = g_s + (size_t)bh * Tn * Tn;
    const int m0 = blockIdx.y * 128, n0 = blockIdx.x * 128;

    float c[4][4][4] = {};

    const int r = tid >> 3, cc = (tid & 7) * 4;
    for (int k0 = 0; k0 < HDn; k0 += 32) {
#pragma unroll
        for (int p = 0; p < 4; p++) {
            int row = r + p * 32;
            *(float4*)&Qs[row][cc] = *(const float4*)&Q[(size_t)(m0 + row) * HDn + k0 + cc];
            *(float4*)&Ks[row][cc] = *(const float4*)&K[(size_t)(n0 + row) * HDn + k0 + cc];
        }
        __syncthreads();
#pragma unroll
        for (int ks = 0; ks < 4; ks++) {
            const int kk = ks * 8;
            unsigned af[4][4], bf[4][2];
#pragma unroll
            for (int tm = 0; tm < 4; tm++) {
                int mr = warp_m * 64 + tm * 16;
                af[tm][0] = f2tf(Qs[mr + g][kk + tig]);
                af[tm][1] = f2tf(Qs[mr + g + 8][kk + tig]);
                af[tm][2] = f2tf(Qs[mr + g][kk + tig + 4]);
                af[tm][3] = f2tf(Qs[mr + g + 8][kk + tig + 4]);
            }
#pragma unroll
            for (int tn = 0; tn < 4; tn++) {
                int nr = warp_n * 32 + tn * 8;
                bf[tn][0] = f2tf(Ks[nr + g][kk + tig]);
                bf[tn][1] = f2tf(Ks[nr + g][kk + tig + 4]);
            }
#pragma unroll
            for (int tm = 0; tm < 4; tm++)
#pragma unroll
                for (int tn = 0; tn < 4; tn++)
                    mma_tf32(c[tm][tn], af[tm], bf[tn]);
        }
        __syncthreads();
    }

#pragma unroll
    for (int tm = 0; tm < 4; tm++) {
        int mr = m0 + warp_m * 64 + tm * 16;
#pragma unroll
        for (int tn = 0; tn < 4; tn++) {
            int nc = n0 + warp_n * 32 + tn * 8 + 2 * tig;
            *(float2*)&S[(size_t)(mr + g) * Tn + nc] =
                make_float2(c[tm][tn][0], c[tm][tn][1]);
            *(float2*)&S[(size_t)(mr + g + 8) * Tn + nc] =
                make_float2(c[tm][tn][2], c[tm][tn][3]);
        }
    }
}

// ---------------------------------------------------------------------------
// Kernel 3: fused softmax (in place on g_s) + head-average.
// One CTA per (b,q) row pair; loops over 8 heads; accumulates avg in regs.
// ---------------------------------------------------------------------------
__global__ __launch_bounds__(256) void k_smax_avg(float* __restrict__ avg) {
    __shared__ float redA[8];
    __shared__ float redB[8];
    const int rI = blockIdx.x;          // b*T + q
    const int b = rI >> 11, q = rI & 2047;
    const int tid = threadIdx.x;
    const int lane = tid & 31, wid = tid >> 5;

    float acc[8];
#pragma unroll
    for (int i = 0; i < 8; i++) acc[i] = 0.f;

    for (int h = 0; h < Hn; h++) {
        const size_t base = ((size_t)(b * Hn + h) * Tn + q) * Tn;
        float4 v0 = *(const float4*)&g_s[base + tid * 4];
        float4 v1 = *(const float4*)&g_s[base + 1024 + tid * 4];

        float m = fmaxf(fmaxf(fmaxf(v0.x, v0.y), fmaxf(v0.z, v0.w)),
                        fmaxf(fmaxf(v1.x, v1.y), fmaxf(v1.z, v1.w)));
#pragma unroll
        for (int o = 16; o; o >>= 1) m = fmaxf(m, __shfl_xor_sync(0xffffffffu, m, o));
        if (lane == 0) redA[wid] = m;
        __syncthreads();
        m = redA[0];
#pragma unroll
        for (int i = 1; i < 8; i++) m = fmaxf(m, redA[i]);

        v0.x = __expf(v0.x - m); v0.y = __expf(v0.y - m);
        v0.z = __expf(v0.z - m); v0.w = __expf(v0.w - m);
        v1.x = __expf(v1.x - m); v1.y = __expf(v1.y - m);
        v1.z = __expf(v1.z - m); v1.w = __expf(v1.w - m);

        float s = v0.x + v0.y + v0.z + v0.w + v1.x + v1.y + v1.z + v1.w;
#pragma unroll
        for (int o = 16; o; o >>= 1) s += __shfl_xor_sync(0xffffffffu, s, o);
        if (lane == 0) redB[wid] = s;
        __syncthreads();
        float tot = 0.f;
#pragma unroll
        for (int i = 0; i < 8; i++) tot += redB[i];
        const float inv = 1.0f / tot;

        v0.x *= inv; v0.y *= inv; v0.z *= inv; v0.w *= inv;
        v1.x *= inv; v1.y *= inv; v1.z *= inv; v1.w *= inv;
        *(float4*)&g_s[base + tid * 4] = v0;
        *(float4*)&g_s[base + 1024 + tid * 4] = v1;

        acc[0] += v0.x; acc[1] += v0.y; acc[2] += v0.z; acc[3] += v0.w;
        acc[4] += v1.x; acc[5] += v1.y; acc[6] += v1.z; acc[7] += v1.w;
    }

    const size_t obase = (size_t)rI * Tn;
    float4 o0 = make_float4(acc[0] * 0.125f, acc[1] * 0.125f,
                            acc[2] * 0.125f, acc[3] * 0.125f);
    float4 o1 = make_float4(acc[4] * 0.125f, acc[5] * 0.125f,
                            acc[6] * 0.125f, acc[7] * 0.125f);
    *(float4*)&avg[obase + tid * 4] = o0;
    *(float4*)&avg[obase + 1024 + tid * 4] = o1;
}

// ---------------------------------------------------------------------------
// Kernel 4: O = P @ V per (b,h), tf32 mma. CTA tile 128(M)x64(N), K-chunk 32.
// 8 warps as 4(m) x 2(n); warp tile 32x32 = 2x4 m16n8 mma tiles.
// B read from pre-transposed g_vt (conflict-free fragment LDS).
// ---------------------------------------------------------------------------
__global__ __launch_bounds__(256) void k_pv_mma() {
    __shared__ float Ps[128][36];
    __shared__ float Vs[64][36];     // Vs[d][k]
    const int tid = threadIdx.x;
    const int wid = tid >> 5, lane = tid & 31;
    const int g = lane >> 2, tig = lane & 3;
    const int warp_m = wid >> 1, warp_n = wid & 1;
    const int bh = blockIdx.z;
    const float* P = g_s + (size_t)bh * Tn * Tn;
    const float* Vt = g_vt + (size_t)bh * HDn * Tn;
    const int m0 = blockIdx.y * 128;

    float c[2][4][4] = {};

    const int r = tid >> 3, cc = (tid & 7) * 4;
    for (int k0 = 0; k0 < Tn; k0 += 32) {
#pragma unroll
        for (int p = 0; p < 4; p++) {
            int row = r + p * 32;
            *(float4*)&Ps[row][cc] = *(const float4*)&P[(size_t)(m0 + row) * Tn + k0 + cc];
        }
#pragma unroll
        for (int p = 0; p < 2; p++) {
            int row = r + p * 32;
            *(float4*)&Vs[row][cc] = *(const float4*)&Vt[(size_t)row * Tn + k0 + cc];
        }
        __syncthreads();
#pragma unroll
        for (int ks = 0; ks < 4; ks++) {
            const int kk = ks * 8;
            unsigned af[2][4], bf[4][2];
#pragma unroll
            for (int tm = 0; tm < 2; tm++) {
                int mr = warp_m * 32 + tm * 16;
                af[tm][0] = f2tf(Ps[mr + g][kk + tig]);
                af[tm][1] = f2tf(Ps[mr + g + 8][kk + tig]);
                af[tm][2] = f2tf(Ps[mr + g][kk + tig + 4]);
                af[tm][3] = f2tf(Ps[mr + g + 8][kk + tig + 4]);
            }
#pragma unroll
            for (int tn = 0; tn < 4; tn++) {
                int nr = warp_n * 32 + tn * 8;
                bf[tn][0] = f2tf(Vs[nr + g][kk + tig]);
                bf[tn][1] = f2tf(Vs[nr + g][kk + tig + 4]);
            }
#pragma unroll
            for (int tm = 0; tm < 2; tm++)
#pragma unroll
                for (int tn = 0; tn < 4; tn++)
                    mma_tf32(c[tm][tn], af[tm], bf[tn]);
        }
        __syncthreads();
    }

#pragma unroll
    for (int tm = 0; tm < 2; tm++) {
        int mr = m0 + warp_m * 32 + tm * 16;
#pragma unroll
        for (int tn = 0; tn < 4; tn++) {
            int nc = warp_n * 32 + tn * 8 + 2 * tig;
            *(float2*)&g_o[((size_t)bh * Tn + mr + g) * HDn + nc] =
                make_float2(c[tm][tn][0], c[tm][tn][1]);
            *(float2*)&g_o[((size_t)bh * Tn + mr + g + 8) * HDn + nc] =
                make_float2(c[tm][tn][2], c[tm][tn][3]);
        }
    }
}

// ---------------------------------------------------------------------------
// Kernel 5: out projection (scalar, unchanged).
// ---------------------------------------------------------------------------
__global__ __launch_bounds__(256) void k_outproj(const float* __restrict__ W2,
                                                 const float* __restrict__ B2,
                                                 float* __restrict__ out) {
    __shared__ float As[16][132];
    __shared__ float Bs[16][132];
    const int tid = threadIdx.x;
    const int tx = tid & 15, ty = tid >> 4;
    const int m0 = blockIdx.y * 128, n0 = blockIdx.x * 128;
    const int lrow = tid >> 2;
    const int lk4 = (tid & 3) << 2;

    float acc[8][8];
#pragma unroll
    for (int i = 0; i < 8; i++)
#pragma unroll
        for (int j = 0; j < 8; j++) acc[i][j] = 0.f;

    for (int k0 = 0; k0 < En; k0 += 16) {
        int e = k0 + lk4;
        int h = e >> 6, d = e & 63;
#pragma unroll
        for (int hh = 0; hh < 2; hh++) {
            int r = lrow + hh * 64;
            int m = m0 + r;
            int t = m >> 2, b = m & 3;
            float4 av = *(const float4*)&g_o[((size_t)(b * Hn + h) * Tn + t) * HDn + d];
            As[lk4 + 0][r] = av.x; As[lk4 + 1][r] = av.y;
            As[lk4 + 2][r] = av.z; As[lk4 + 3][r] = av.w;
            float4 bv = *(const float4*)&W2[(size_t)(n0 + r) * En + k0 + lk4];
            Bs[lk4 + 0][r] = bv.x; Bs[lk4 + 1][r] = bv.y;
            Bs[lk4 + 2][r] = bv.z; Bs[lk4 + 3][r] = bv.w;
        }
        __syncthreads();
#pragma unroll
        for (int kk = 0; kk < 16; kk++) {
            float a[8], b[8];
            *(float4*)(a)     = *(const float4*)&As[kk][ty * 4];
            *(float4*)(a + 4) = *(const float4*)&As[kk][64 + ty * 4];
            *(float4*)(b)     = *(const float4*)&Bs[kk][tx * 4];
            *(float4*)(b + 4) = *(const float4*)&Bs[kk][64 + tx * 4];
#pragma unroll
            for (int i = 0; i < 8; i++)
#pragma unroll
                for (int j = 0; j < 8; j++) acc[i][j] += a[i] * b[j];
        }
        __syncthreads();
    }

#pragma unroll
    for (int i = 0; i < 8; i++) {
        int m = m0 + ((i < 4) ? (ty * 4 + i) : (64 + ty * 4 + (i - 4)));
#pragma unroll
        for (int jh = 0; jh < 2; jh++) {
            int n = n0 + jh * 64 + tx * 4;
            float4 v;
            v.x = acc[i][jh * 4 + 0] + B2[n + 0];
            v.y = acc[i][jh * 4 + 1] + B2[n + 1];
            v.z = acc[i][jh * 4 + 2] + B2[n + 2];
            v.w = acc[i][jh * 4 + 3] + B2[n + 3];
            *(float4*)&out[(size_t)m * En + n] = v;
        }
    }
}

// ---------------------------------------------------------------------------
extern "C" void kernel_launch(void* const* d_in, const int* in_sizes, int n_in,
                              void* d_out, int out_size) {
    (void)in_sizes; (void)n_in; (void)out_size;
    const float* x  = (const float*)d_in[0];
    const float* w  = (const float*)d_in[1];
    const float* bi = (const float*)d_in[2];
    const float* w2 = (const float*)d_in[3];
    const float* b2 = (const float*)d_in[4];
    float* out = (float*)d_out;

    k_qkv<<<dim3(12, 64), 256>>>(x, w, bi);                 // QKV projection
    k_vt<<<dim3(64, 2, 32), 256>>>();                       // V transpose
    k_scores_mma<<<dim3(16, 16, 32), 256>>>();              // S = Q K^T (tf32)
    k_smax_avg<<<Bn * Tn, 256>>>(out + (size_t)TBn * En);   // softmax + head-avg
    k_pv_mma<<<dim3(1, 16, 32), 256>>>();                   // O = P V (tf32)
    k_outproj<<<dim3(4, 64), 256>>>(w2, b2, out);           // out projection
}

// round 5
// speedup vs baseline: 1.5690x; 1.0033x over previous
#include <cuda_runtime.h>
#include <math.h>

#define Tn 2048
#define Bn 4
#define En 512
#define Hn 8
#define HDn 64
#define BHn 32
#define TBn 8192
#define SCALE_F 0.125f

// Scratch (allocation-free rule: __device__ globals)
__device__ float g_q[BHn * Tn * HDn];          // [b*H+h][t][d], pre-scaled
__device__ float g_k[BHn * Tn * HDn];
__device__ float g_v[BHn * Tn * HDn];
__device__ float g_vt[BHn * HDn * Tn];         // V transposed: [bh][d][t]
__device__ float g_o[BHn * Tn * HDn];          // attention output pre-projection
__device__ float g_s[134217728];               // [b*H+h][q][k]  (536 MB)

// ---------------------------------------------------------------------------
// tf32 mma helpers
// ---------------------------------------------------------------------------
__device__ __forceinline__ unsigned f2tf(float x) {
    unsigned r;
    asm("cvt.rna.tf32.f32 %0, %1;" : "=r"(r) : "f"(x));
    return r;
}

__device__ __forceinline__ void mma_tf32(float* c, const unsigned* a, const unsigned* b) {
    asm volatile(
        "mma.sync.aligned.m16n8k8.row.col.f32.tf32.tf32.f32 "
        "{%0,%1,%2,%3}, {%4,%5,%6,%7}, {%8,%9}, {%0,%1,%2,%3};"
        : "+f"(c[0]), "+f"(c[1]), "+f"(c[2]), "+f"(c[3])
        : "r"(a[0]), "r"(a[1]), "r"(a[2]), "r"(a[3]), "r"(b[0]), "r"(b[1]));
}

// ---------------------------------------------------------------------------
// Kernel 1: QKV projection (scalar, unchanged).
// ---------------------------------------------------------------------------
__global__ __launch_bounds__(256) void k_qkv(const float* __restrict__ X,
                                             const float* __restrict__ W,
                                             const float* __restrict__ Bv) {
    __shared__ float As[16][132];
    __shared__ float Bs[16][132];
    const int tid = threadIdx.x;
    const int tx = tid & 15, ty = tid >> 4;
    const int m0 = blockIdx.y * 128, n0 = blockIdx.x * 128;
    const int lrow = tid >> 2;
    const int lk4 = (tid & 3) << 2;

    float acc[8][8];
#pragma unroll
    for (int i = 0; i < 8; i++)
#pragma unroll
        for (int j = 0; j < 8; j++) acc[i][j] = 0.f;

    for (int k0 = 0; k0 < En; k0 += 16) {
#pragma unroll
        for (int hh = 0; hh < 2; hh++) {
            int r = lrow + hh * 64;
            float4 av = *(const float4*)&X[(size_t)(m0 + r) * En + k0 + lk4];
            As[lk4 + 0][r] = av.x; As[lk4 + 1][r] = av.y;
            As[lk4 + 2][r] = av.z; As[lk4 + 3][r] = av.w;
            float4 bv = *(const float4*)&W[(size_t)(n0 + r) * En + k0 + lk4];
            Bs[lk4 + 0][r] = bv.x; Bs[lk4 + 1][r] = bv.y;
            Bs[lk4 + 2][r] = bv.z; Bs[lk4 + 3][r] = bv.w;
        }
        __syncthreads();
#pragma unroll
        for (int kk = 0; kk < 16; kk++) {
            float a[8], b[8];
            *(float4*)(a)     = *(const float4*)&As[kk][ty * 4];
            *(float4*)(a + 4) = *(const float4*)&As[kk][64 + ty * 4];
            *(float4*)(b)     = *(const float4*)&Bs[kk][tx * 4];
            *(float4*)(b + 4) = *(const float4*)&Bs[kk][64 + tx * 4];
#pragma unroll
            for (int i = 0; i < 8; i++)
#pragma unroll
                for (int j = 0; j < 8; j++) acc[i][j] += a[i] * b[j];
        }
        __syncthreads();
    }

    const int which = n0 >> 9;
    float* dst = which == 0 ? g_q : (which == 1 ? g_k : g_v);
    const float mul = (which == 0) ? SCALE_F : 1.0f;

#pragma unroll
    for (int i = 0; i < 8; i++) {
        int m = m0 + ((i < 4) ? (ty * 4 + i) : (64 + ty * 4 + (i - 4)));
        int t = m >> 2, b = m & 3;
#pragma unroll
        for (int jh = 0; jh < 2; jh++) {
            int n = n0 + jh * 64 + tx * 4;
            int e = n & 511;
            int h = e >> 6, d = e & 63;
            float4 v;
            v.x = (acc[i][jh * 4 + 0] + Bv[n + 0]) * mul;
            v.y = (acc[i][jh * 4 + 1] + Bv[n + 1]) * mul;
            v.z = (acc[i][jh * 4 + 2] + Bv[n + 2]) * mul;
            v.w = (acc[i][jh * 4 + 3] + Bv[n + 3]) * mul;
            *(float4*)&dst[((size_t)(b * Hn + h) * Tn + t) * HDn + d] = v;
        }
    }
}

// ---------------------------------------------------------------------------
// Kernel 1b: V transpose  g_vt[bh][d][t] = g_v[bh][t][d]
// ---------------------------------------------------------------------------
__global__ __launch_bounds__(256) void k_vt() {
    __shared__ float ts[32][33];
    const int bh = blockIdx.z;
    const int t0 = blockIdx.x * 32, d0 = blockIdx.y * 32;
    const float* V = g_v + (size_t)bh * Tn * HDn;
    float* Vt = g_vt + (size_t)bh * HDn * Tn;
    const int lx = threadIdx.x & 31, ly = threadIdx.x >> 5;
#pragma unroll
    for (int p = 0; p < 4; p++) {
        int row = ly + p * 8;
        ts[row][lx] = V[(size_t)(t0 + row) * HDn + d0 + lx];
    }
    __syncthreads();
#pragma unroll
    for (int p = 0; p < 4; p++) {
        int row = ly + p * 8;
        Vt[(size_t)(d0 + row) * Tn + t0 + lx] = ts[lx][row];
    }
}

// ---------------------------------------------------------------------------
// Kernel 2: scores S = Q @ K^T per (b,h), tf32 mma. CTA tile 128x128, K=64.
// 8 warps as 2(m) x 4(n); warp tile 64x32 = 4x4 m16n8 mma tiles.
// ---------------------------------------------------------------------------
__global__ __launch_bounds__(256) void k_scores_mma() {
    __shared__ float Qs[128][36];
    __shared__ float Ks[128][36];
    const int tid = threadIdx.x;
    const int wid = tid >> 5, lane = tid & 31;
    const int g = lane >> 2, tig = lane & 3;
    const int warp_m = wid >> 2, warp_n = wid & 3;
    const int bh = blockIdx.z;
    const float* Q = g_q + (size_t)bh * Tn * HDn;
    const float* K = g_k + (size_t)bh * Tn * HDn;
    float* S = g_s + (size_t)bh * Tn * Tn;
    const int m0 = blockIdx.y * 128, n0 = blockIdx.x * 128;

    float c[4][4][4] = {};

    const int r = tid >> 3, cc = (tid & 7) * 4;
    for (int k0 = 0; k0 < HDn; k0 += 32) {
#pragma unroll
        for (int p = 0; p < 4; p++) {
            int row = r + p * 32;
            *(float4*)&Qs[row][cc] = *(const float4*)&Q[(size_t)(m0 + row) * HDn + k0 + cc];
            *(float4*)&Ks[row][cc] = *(const float4*)&K[(size_t)(n0 + row) * HDn + k0 + cc];
        }
        __syncthreads();
#pragma unroll
        for (int ks = 0; ks < 4; ks++) {
            const int kk = ks * 8;
            unsigned af[4][4], bf[4][2];
#pragma unroll
            for (int tm = 0; tm < 4; tm++) {
                int mr = warp_m * 64 + tm * 16;
                af[tm][0] = f2tf(Qs[mr + g][kk + tig]);
                af[tm][1] = f2tf(Qs[mr + g + 8][kk + tig]);
                af[tm][2] = f2tf(Qs[mr + g][kk + tig + 4]);
                af[tm][3] = f2tf(Qs[mr + g + 8][kk + tig + 4]);
            }
#pragma unroll
            for (int tn = 0; tn < 4; tn++) {
                int nr = warp_n * 32 + tn * 8;
                bf[tn][0] = f2tf(Ks[nr + g][kk + tig]);
                bf[tn][1] = f2tf(Ks[nr + g][kk + tig + 4]);
            }
#pragma unroll
            for (int tm = 0; tm < 4; tm++)
#pragma unroll
                for (int tn = 0; tn < 4; tn++)
                    mma_tf32(c[tm][tn], af[tm], bf[tn]);
        }
        __syncthreads();
    }

#pragma unroll
    for (int tm = 0; tm < 4; tm++) {
        int mr = m0 + warp_m * 64 + tm * 16;
#pragma unroll
        for (int tn = 0; tn < 4; tn++) {
            int nc = n0 + warp_n * 32 + tn * 8 + 2 * tig;
            *(float2*)&S[(size_t)(mr + g) * Tn + nc] =
                make_float2(c[tm][tn][0], c[tm][tn][1]);
            *(float2*)&S[(size_t)(mr + g + 8) * Tn + nc] =
                make_float2(c[tm][tn][2], c[tm][tn][3]);
        }
    }
}

// ---------------------------------------------------------------------------
// Kernel 3: fused softmax (in place on g_s) + head-average.
// One CTA per (b,q) row pair; loops over 8 heads; accumulates avg in regs.
// ---------------------------------------------------------------------------
__global__ __launch_bounds__(256) void k_smax_avg(float* __restrict__ avg) {
    __shared__ float redA[8];
    __shared__ float redB[8];
    const int rI = blockIdx.x;          // b*T + q
    const int b = rI >> 11, q = rI & 2047;
    const int tid = threadIdx.x;
    const int lane = tid & 31, wid = tid >> 5;

    float acc[8];
#pragma unroll
    for (int i = 0; i < 8; i++) acc[i] = 0.f;

    for (int h = 0; h < Hn; h++) {
        const size_t base = ((size_t)(b * Hn + h) * Tn + q) * Tn;
        float4 v0 = *(const float4*)&g_s[base + tid * 4];
        float4 v1 = *(const float4*)&g_s[base + 1024 + tid * 4];

        float m = fmaxf(fmaxf(fmaxf(v0.x, v0.y), fmaxf(v0.z, v0.w)),
                        fmaxf(fmaxf(v1.x, v1.y), fmaxf(v1.z, v1.w)));
#pragma unroll
        for (int o = 16; o; o >>= 1) m = fmaxf(m, __shfl_xor_sync(0xffffffffu, m, o));
        if (lane == 0) redA[wid] = m;
        __syncthreads();
        m = redA[0];
#pragma unroll
        for (int i = 1; i < 8; i++) m = fmaxf(m, redA[i]);

        v0.x = __expf(v0.x - m); v0.y = __expf(v0.y - m);
        v0.z = __expf(v0.z - m); v0.w = __expf(v0.w - m);
        v1.x = __expf(v1.x - m); v1.y = __expf(v1.y - m);
        v1.z = __expf(v1.z - m); v1.w = __expf(v1.w - m);

        float s = v0.x + v0.y + v0.z + v0.w + v1.x + v1.y + v1.z + v1.w;
#pragma unroll
        for (int o = 16; o; o >>= 1) s += __shfl_xor_sync(0xffffffffu, s, o);
        if (lane == 0) redB[wid] = s;
        __syncthreads();
        float tot = 0.f;
#pragma unroll
        for (int i = 0; i < 8; i++) tot += redB[i];
        const float inv = 1.0f / tot;

        v0.x *= inv; v0.y *= inv; v0.z *= inv; v0.w *= inv;
        v1.x *= inv; v1.y *= inv; v1.z *= inv; v1.w *= inv;
        *(float4*)&g_s[base + tid * 4] = v0;
        *(float4*)&g_s[base + 1024 + tid * 4] = v1;

        acc[0] += v0.x; acc[1] += v0.y; acc[2] += v0.z; acc[3] += v0.w;
        acc[4] += v1.x; acc[5] += v1.y; acc[6] += v1.z; acc[7] += v1.w;
    }

    const size_t obase = (size_t)rI * Tn;
    float4 o0 = make_float4(acc[0] * 0.125f, acc[1] * 0.125f,
                            acc[2] * 0.125f, acc[3] * 0.125f);
    float4 o1 = make_float4(acc[4] * 0.125f, acc[5] * 0.125f,
                            acc[6] * 0.125f, acc[7] * 0.125f);
    *(float4*)&avg[obase + tid * 4] = o0;
    *(float4*)&avg[obase + 1024 + tid * 4] = o1;
}

// ---------------------------------------------------------------------------
// Kernel 4: O = P @ V per (b,h), tf32 mma. CTA tile 128(M)x64(N), K-chunk 32.
// 8 warps as 4(m) x 2(n); warp tile 32x32 = 2x4 m16n8 mma tiles.
// B read from pre-transposed g_vt (conflict-free fragment LDS).
// ---------------------------------------------------------------------------
__global__ __launch_bounds__(256) void k_pv_mma() {
    __shared__ float Ps[128][36];
    __shared__ float Vs[64][36];     // Vs[d][k]
    const int tid = threadIdx.x;
    const int wid = tid >> 5, lane = tid & 31;
    const int g = lane >> 2, tig = lane & 3;
    const int warp_m = wid >> 1, warp_n = wid & 1;
    const int bh = blockIdx.z;
    const float* P = g_s + (size_t)bh * Tn * Tn;
    const float* Vt = g_vt + (size_t)bh * HDn * Tn;
    const int m0 = blockIdx.y * 128;

    float c[2][4][4] = {};

    const int r = tid >> 3, cc = (tid & 7) * 4;
    for (int k0 = 0; k0 < Tn; k0 += 32) {
#pragma unroll
        for (int p = 0; p < 4; p++) {
            int row = r + p * 32;
            *(float4*)&Ps[row][cc] = *(const float4*)&P[(size_t)(m0 + row) * Tn + k0 + cc];
        }
#pragma unroll
        for (int p = 0; p < 2; p++) {
            int row = r + p * 32;
            *(float4*)&Vs[row][cc] = *(const float4*)&Vt[(size_t)row * Tn + k0 + cc];
        }
        __syncthreads();
#pragma unroll
        for (int ks = 0; ks < 4; ks++) {
            const int kk = ks * 8;
            unsigned af[2][4], bf[4][2];
#pragma unroll
            for (int tm = 0; tm < 2; tm++) {
                int mr = warp_m * 32 + tm * 16;
                af[tm][0] = f2tf(Ps[mr + g][kk + tig]);
                af[tm][1] = f2tf(Ps[mr + g + 8][kk + tig]);
                af[tm][2] = f2tf(Ps[mr + g][kk + tig + 4]);
                af[tm][3] = f2tf(Ps[mr + g + 8][kk + tig + 4]);
            }
#pragma unroll
            for (int tn = 0; tn < 4; tn++) {
                int nr = warp_n * 32 + tn * 8;
                bf[tn][0] = f2tf(Vs[nr + g][kk + tig]);
                bf[tn][1] = f2tf(Vs[nr + g][kk + tig + 4]);
            }
#pragma unroll
            for (int tm = 0; tm < 2; tm++)
#pragma unroll
                for (int tn = 0; tn < 4; tn++)
                    mma_tf32(c[tm][tn], af[tm], bf[tn]);
        }
        __syncthreads();
    }

#pragma unroll
    for (int tm = 0; tm < 2; tm++) {
        int mr = m0 + warp_m * 32 + tm * 16;
#pragma unroll
        for (int tn = 0; tn < 4; tn++) {
            int nc = warp_n * 32 + tn * 8 + 2 * tig;
            *(float2*)&g_o[((size_t)bh * Tn + mr + g) * HDn + nc] =
                make_float2(c[tm][tn][0], c[tm][tn][1]);
            *(float2*)&g_o[((size_t)bh * Tn + mr + g + 8) * HDn + nc] =
                make_float2(c[tm][tn][2], c[tm][tn][3]);
        }
    }
}

// ---------------------------------------------------------------------------
// Kernel 5: out projection (scalar, unchanged).
// ---------------------------------------------------------------------------
__global__ __launch_bounds__(256) void k_outproj(const float* __restrict__ W2,
                                                 const float* __restrict__ B2,
                                                 float* __restrict__ out) {
    __shared__ float As[16][132];
    __shared__ float Bs[16][132];
    const int tid = threadIdx.x;
    const int tx = tid & 15, ty = tid >> 4;
    const int m0 = blockIdx.y * 128, n0 = blockIdx.x * 128;
    const int lrow = tid >> 2;
    const int lk4 = (tid & 3) << 2;

    float acc[8][8];
#pragma unroll
    for (int i = 0; i < 8; i++)
#pragma unroll
        for (int j = 0; j < 8; j++) acc[i][j] = 0.f;

    for (int k0 = 0; k0 < En; k0 += 16) {
        int e = k0 + lk4;
        int h = e >> 6, d = e & 63;
#pragma unroll
        for (int hh = 0; hh < 2; hh++) {
            int r = lrow + hh * 64;
            int m = m0 + r;
            int t = m >> 2, b = m & 3;
            float4 av = *(const float4*)&g_o[((size_t)(b * Hn + h) * Tn + t) * HDn + d];
            As[lk4 + 0][r] = av.x; As[lk4 + 1][r] = av.y;
            As[lk4 + 2][r] = av.z; As[lk4 + 3][r] = av.w;
            float4 bv = *(const float4*)&W2[(size_t)(n0 + r) * En + k0 + lk4];
            Bs[lk4 + 0][r] = bv.x; Bs[lk4 + 1][r] = bv.y;
            Bs[lk4 + 2][r] = bv.z; Bs[lk4 + 3][r] = bv.w;
        }
        __syncthreads();
#pragma unroll
        for (int kk = 0; kk < 16; kk++) {
            float a[8], b[8];
            *(float4*)(a)     = *(const float4*)&As[kk][ty * 4];
            *(float4*)(a + 4) = *(const float4*)&As[kk][64 + ty * 4];
            *(float4*)(b)     = *(const float4*)&Bs[kk][tx * 4];
            *(float4*)(b + 4) = *(const float4*)&Bs[kk][64 + tx * 4];
#pragma unroll
            for (int i = 0; i < 8; i++)
#pragma unroll
                for (int j = 0; j < 8; j++) acc[i][j] += a[i] * b[j];
        }
        __syncthreads();
    }

#pragma unroll
    for (int i = 0; i < 8; i++) {
        int m = m0 + ((i < 4) ? (ty * 4 + i) : (64 + ty * 4 + (i - 4)));
#pragma unroll
        for (int jh = 0; jh < 2; jh++) {
            int n = n0 + jh * 64 + tx * 4;
            float4 v;
            v.x = acc[i][jh * 4 + 0] + B2[n + 0];
            v.y = acc[i][jh * 4 + 1] + B2[n + 1];
            v.z = acc[i][jh * 4 + 2] + B2[n + 2];
            v.w = acc[i][jh * 4 + 3] + B2[n + 3];
            *(float4*)&out[(size_t)m * En + n] = v;
        }
    }
}

// ---------------------------------------------------------------------------
extern "C" void kernel_launch(void* const* d_in, const int* in_sizes, int n_in,
                              void* d_out, int out_size) {
    (void)in_sizes; (void)n_in; (void)out_size;
    const float* x  = (const float*)d_in[0];
    const float* w  = (const float*)d_in[1];
    const float* bi = (const float*)d_in[2];
    const float* w2 = (const float*)d_in[3];
    const float* b2 = (const float*)d_in[4];
    float* out = (float*)d_out;

    k_qkv<<<dim3(12, 64), 256>>>(x, w, bi);                 // QKV projection
    k_vt<<<dim3(64, 2, 32), 256>>>();                       // V transpose
    k_scores_mma<<<dim3(16, 16, 32), 256>>>();              // S = Q K^T (tf32)
    k_smax_avg<<<Bn * Tn, 256>>>(out + (size_t)TBn * En);   // softmax + head-avg
    k_pv_mma<<<dim3(1, 16, 32), 256>>>();                   // O = P V (tf32)
    k_outproj<<<dim3(4, 64), 256>>>(w2, b2, out);           // out projection
}